// round 7
// baseline (speedup 1.0000x reference)
#include <cuda_runtime.h>
#include <math.h>

#define NB 4
#define NP 2048
#define ND 64
#define EPS_F 0.1f
#define THRESH_F 0.1f
#define MAX_ITER 50

static __device__ float g_C[(size_t)NB * NP * NP];   // 64 MB cost matrix
static __device__ float g_u[NB * NP];
static __device__ float g_v[NB * NP];
static __device__ float g_errpart[1024];
static __device__ float g_costpart[1024];
static __device__ int   g_done;

__device__ __forceinline__ float inv_eps() { return 1.0f / EPS_F; }

// L2 evict_last via access policy (ptxas on this toolchain rejects the bare
// .L2::evict_last modifier on .v4.f32; the cache_hint form is accepted).
__device__ __forceinline__ unsigned long long mk_el_policy() {
    unsigned long long p;
    asm("createpolicy.fractional.L2::evict_last.b64 %0, 1.0;" : "=l"(p));
    return p;
}
__device__ __forceinline__ float4 ldg_el4(const float4* p, unsigned long long pol) {
    float4 v;
    asm("ld.global.nc.L2::cache_hint.v4.f32 {%0,%1,%2,%3}, [%4], %5;"
        : "=f"(v.x), "=f"(v.y), "=f"(v.z), "=f"(v.w) : "l"(p), "l"(pol));
    return v;
}
__device__ __forceinline__ void stg_el4(float4* p, float4 v, unsigned long long pol) {
    asm volatile("st.global.L2::cache_hint.v4.f32 [%0], {%1,%2,%3,%4}, %5;"
        :: "l"(p), "f"(v.x), "f"(v.y), "f"(v.z), "f"(v.w), "l"(pol) : "memory");
}

// ---------------------------------------------------------------------------
// init: zero u, v; errpart = huge (first-iteration done check must be false)
// ---------------------------------------------------------------------------
__global__ void k_init() {
    int t = blockIdx.x * blockDim.x + threadIdx.x;
    if (t < NB * NP) { g_u[t] = 0.0f; g_v[t] = 0.0f; }
    if (t < 1024) g_errpart[t] = 1.0e30f;
    if (t == 0) g_done = 0;
}

// ---------------------------------------------------------------------------
// C[b][i][j] = ||x_i||^2 + ||y_j||^2 - 2 * <x_i, y_j>
// grid (32, 32, 4), 256 threads, 64x64 output tile per block
// ---------------------------------------------------------------------------
__global__ void k_cost(const float* __restrict__ x, const float* __restrict__ y) {
    __shared__ __align__(16) float xs[ND][68];
    __shared__ __align__(16) float ys[ND][68];
    __shared__ float nx[64], ny[64];

    int b  = blockIdx.z;
    int i0 = blockIdx.y * 64;
    int j0 = blockIdx.x * 64;
    int tid = threadIdx.x;

    const float* xp = x + ((size_t)b * NP + i0) * ND;
    const float* yp = y + ((size_t)b * NP + j0) * ND;

    for (int idx = tid; idx < 64 * ND; idx += 256) {
        int r = idx >> 6;
        int d = idx & 63;
        xs[d][r] = xp[r * ND + d];
        ys[d][r] = yp[r * ND + d];
    }
    __syncthreads();

    if (tid < 64) {
        float s = 0.0f;
        #pragma unroll 16
        for (int d = 0; d < ND; d++) { float v = xs[d][tid]; s = fmaf(v, v, s); }
        nx[tid] = s;
    } else if (tid < 128) {
        int j = tid - 64;
        float s = 0.0f;
        #pragma unroll 16
        for (int d = 0; d < ND; d++) { float v = ys[d][j]; s = fmaf(v, v, s); }
        ny[j] = s;
    }
    __syncthreads();

    int tx = tid & 15, ty = tid >> 4;
    float acc[4][4] = {};
    #pragma unroll 16
    for (int d = 0; d < ND; d++) {
        float4 xr = *(const float4*)&xs[d][ty * 4];
        float4 yr = *(const float4*)&ys[d][tx * 4];
        float xa[4] = {xr.x, xr.y, xr.z, xr.w};
        float ya[4] = {yr.x, yr.y, yr.z, yr.w};
        #pragma unroll
        for (int a = 0; a < 4; a++)
            #pragma unroll
            for (int c = 0; c < 4; c++)
                acc[a][c] = fmaf(xa[a], ya[c], acc[a][c]);
    }

    unsigned long long pol = mk_el_policy();
    #pragma unroll
    for (int a = 0; a < 4; a++) {
        int i = i0 + ty * 4 + a;
        size_t base = ((size_t)b * NP + i) * NP + j0 + tx * 4;
        float4 o;
        o.x = nx[ty * 4 + a] + ny[tx * 4 + 0] - 2.0f * acc[a][0];
        o.y = nx[ty * 4 + a] + ny[tx * 4 + 1] - 2.0f * acc[a][1];
        o.z = nx[ty * 4 + a] + ny[tx * 4 + 2] - 2.0f * acc[a][2];
        o.w = nx[ty * 4 + a] + ny[tx * 4 + 3] - 2.0f * acc[a][3];
        stg_el4((float4*)&g_C[base], o, pol);
    }
}

// ---------------------------------------------------------------------------
// u update: u_new_i = eps*(log_mu - LSE_j((v_j - C_ij)/eps))
// grid 1024 x 256; warp per row; 8 float4 loads in flight.
// Each block ALSO deterministically reduces last iteration's err partials and
// writes g_done (same value from every block -> race-free "done entering step")
// ---------------------------------------------------------------------------
__global__ __launch_bounds__(256) void k_urow() {
    __shared__ __align__(16) float vs[NP];
    __shared__ float red[256];
    __shared__ float werr[8];
    __shared__ int   sdone;

    int tid = threadIdx.x;
    int rowbase = blockIdx.x * 8;
    int b = rowbase >> 11;

    // overlap v-load with err reduction
    for (int j = tid; j < NP; j += 256) vs[j] = g_v[b * NP + j] * inv_eps();
    {
        float e = 0.0f;
        #pragma unroll
        for (int k = 0; k < 4; k++) e += g_errpart[tid + k * 256];
        red[tid] = e;
    }
    __syncthreads();
    #pragma unroll
    for (int st = 128; st; st >>= 1) {
        if (tid < st) red[tid] += red[tid + st];
        __syncthreads();
    }
    if (tid == 0) {
        int d = (red[0] * (1.0f / (float)NB) < THRESH_F) ? 1 : 0;
        sdone = d;
        g_done = d;       // every block writes the identical value
    }
    __syncthreads();
    if (sdone) return;    // frozen: leave u and errpart untouched

    int w = tid >> 5, lane = tid & 31;
    int row = rowbase + w;
    const float4* Cr = (const float4*)(g_C + (size_t)row * NP);
    const float4* vv = (const float4*)vs;
    unsigned long long pol = mk_el_policy();

    float m = -INFINITY, s = 0.0f;
    #pragma unroll 1
    for (int c = 0; c < 2; c++) {
        float a[32];
        #pragma unroll
        for (int k = 0; k < 8; k++) {
            int q = (c * 8 + k) * 32 + lane;
            float4 Cq = ldg_el4(Cr + q, pol);
            float4 vq = vv[q];
            a[k * 4 + 0] = fmaf(Cq.x, -inv_eps(), vq.x);
            a[k * 4 + 1] = fmaf(Cq.y, -inv_eps(), vq.y);
            a[k * 4 + 2] = fmaf(Cq.z, -inv_eps(), vq.z);
            a[k * 4 + 3] = fmaf(Cq.w, -inv_eps(), vq.w);
        }
        float cm = a[0];
        #pragma unroll
        for (int k = 1; k < 32; k++) cm = fmaxf(cm, a[k]);
        float nm = fmaxf(m, cm);
        s *= __expf(m - nm);
        #pragma unroll
        for (int k = 0; k < 32; k++) s += __expf(a[k] - nm);
        m = nm;
    }
    #pragma unroll
    for (int off = 16; off; off >>= 1) {
        float om = __shfl_down_sync(0xffffffffu, m, off);
        float os = __shfl_down_sync(0xffffffffu, s, off);
        float nm = fmaxf(m, om);
        s = s * __expf(m - nm) + os * __expf(om - nm);
        m = nm;
    }
    if (lane == 0) {
        float lse = m + logf(s);
        float lmu = logf(1.0f / (float)NP + 1e-8f);
        float un  = EPS_F * (lmu - lse);
        float uo  = g_u[row];
        g_u[row]  = un;
        werr[w]   = fabsf(un - uo);
    }
    __syncthreads();
    if (tid == 0) {
        float e = 0.0f;
        #pragma unroll
        for (int k = 0; k < 8; k++) e += werr[k];
        g_errpart[blockIdx.x] = e;
    }
}

// ---------------------------------------------------------------------------
// v update: v_new_j = eps*(log_nu - LSE_i((u_i - C_ij)/eps))    (u = new u)
// grid 64 blocks x 1024 threads; block = (b, 128-col tile).
// Lane owns 4 columns (float4 loads, 512B/warp/row); warp w covers rows
// [w*64, w*64+64). Per-warp (m,s) partials combined in smem, v written direct.
// ---------------------------------------------------------------------------
__global__ __launch_bounds__(1024) void k_vcol() {
    if (*(volatile int*)&g_done) return; // value written by this step's k_urow
    __shared__ float us[NP];            // 8KB
    __shared__ float smM[32][128];      // 16KB
    __shared__ float smS[32][128];      // 16KB

    int tid = threadIdx.x;
    int b  = blockIdx.x >> 4;
    int j0 = (blockIdx.x & 15) * 128;

    for (int i = tid; i < NP; i += 1024) us[i] = g_u[b * NP + i] * inv_eps();
    __syncthreads();

    int w = tid >> 5, lane = tid & 31;
    const float4* Cb = (const float4*)(g_C + (size_t)b * NP * NP) + (j0 >> 2) + lane;
    int rbase = w * 64;
    unsigned long long pol = mk_el_policy();

    float4 m4 = make_float4(-INFINITY, -INFINITY, -INFINITY, -INFINITY);
    float4 s4 = make_float4(0.0f, 0.0f, 0.0f, 0.0f);

    #pragma unroll 1
    for (int c = 0; c < 8; c++) {
        float4 a[8];
        int ib = rbase + c * 8;
        #pragma unroll
        for (int k = 0; k < 8; k++) {
            float4 Cq = ldg_el4(Cb + (size_t)(ib + k) * (NP / 4), pol);
            float ui  = us[ib + k];
            a[k].x = fmaf(Cq.x, -inv_eps(), ui);
            a[k].y = fmaf(Cq.y, -inv_eps(), ui);
            a[k].z = fmaf(Cq.z, -inv_eps(), ui);
            a[k].w = fmaf(Cq.w, -inv_eps(), ui);
        }
        #define LSE_COMP(F) { \
            float cm = a[0].F; \
            _Pragma("unroll") \
            for (int k = 1; k < 8; k++) cm = fmaxf(cm, a[k].F); \
            float nm = fmaxf(m4.F, cm); \
            s4.F *= __expf(m4.F - nm); \
            _Pragma("unroll") \
            for (int k = 0; k < 8; k++) s4.F += __expf(a[k].F - nm); \
            m4.F = nm; }
        LSE_COMP(x) LSE_COMP(y) LSE_COMP(z) LSE_COMP(w)
        #undef LSE_COMP
    }

    *(float4*)&smM[w][lane * 4] = m4;
    *(float4*)&smS[w][lane * 4] = s4;
    __syncthreads();

    if (tid < 128) {
        float M = smM[0][tid];
        #pragma unroll
        for (int k = 1; k < 32; k++) M = fmaxf(M, smM[k][tid]);
        float S = 0.0f;
        #pragma unroll
        for (int k = 0; k < 32; k++) S += smS[k][tid] * __expf(smM[k][tid] - M);
        float lse = M + logf(S);
        float lnu = logf(1.0f / (float)NP + 1e-8f);
        g_v[b * NP + j0 + tid] = EPS_F * (lnu - lse);
    }
}

// ---------------------------------------------------------------------------
// final: cost partials  sum_ij exp((u_i + v_j - C)/eps) * C ; float4 loads
// ---------------------------------------------------------------------------
__global__ __launch_bounds__(256) void k_final() {
    __shared__ __align__(16) float vs[NP];
    __shared__ float wsum[8];

    int tid = threadIdx.x;
    int rowbase = blockIdx.x * 8;
    int b = rowbase >> 11;

    for (int j = tid; j < NP; j += 256) vs[j] = g_v[b * NP + j] * inv_eps();
    __syncthreads();

    int w = tid >> 5, lane = tid & 31;
    int row = rowbase + w;
    const float4* Cr = (const float4*)(g_C + (size_t)row * NP);
    const float4* vv = (const float4*)vs;
    float uie = g_u[row] * inv_eps();
    unsigned long long pol = mk_el_policy();

    float acc = 0.0f;
    #pragma unroll 4
    for (int t = 0; t < 16; t++) {
        int q = t * 32 + lane;
        float4 Cq = ldg_el4(Cr + q, pol);
        float4 vq = vv[q];
        float e0 = __expf(fmaf(Cq.x, -inv_eps(), uie + vq.x));
        float e1 = __expf(fmaf(Cq.y, -inv_eps(), uie + vq.y));
        float e2 = __expf(fmaf(Cq.z, -inv_eps(), uie + vq.z));
        float e3 = __expf(fmaf(Cq.w, -inv_eps(), uie + vq.w));
        acc = fmaf(e0, Cq.x, acc);
        acc = fmaf(e1, Cq.y, acc);
        acc = fmaf(e2, Cq.z, acc);
        acc = fmaf(e3, Cq.w, acc);
    }
    #pragma unroll
    for (int off = 16; off; off >>= 1)
        acc += __shfl_down_sync(0xffffffffu, acc, off);
    if (lane == 0) wsum[w] = acc;
    __syncthreads();
    if (tid == 0) {
        float e = 0.0f;
        #pragma unroll
        for (int k = 0; k < 8; k++) e += wsum[k];
        g_costpart[blockIdx.x] = e;
    }
}

__global__ void k_reduce(float* out) {
    __shared__ float red[256];
    int tid = threadIdx.x;
    float e = 0.0f;
    for (int k = tid; k < 1024; k += 256) e += g_costpart[k];
    red[tid] = e;
    __syncthreads();
    for (int st = 128; st; st >>= 1) {
        if (tid < st) red[tid] += red[tid + st];
        __syncthreads();
    }
    if (tid == 0) out[0] = red[0] * (1.0f / (float)NB);
}

// ---------------------------------------------------------------------------
extern "C" void kernel_launch(void* const* d_in, const int* in_sizes, int n_in,
                              void* d_out, int out_size) {
    const float* x = (const float*)d_in[0];
    const float* y = (const float*)d_in[1];
    float* out = (float*)d_out;

    k_init<<<32, 256>>>();
    dim3 gc(32, 32, 4);
    k_cost<<<gc, 256>>>(x, y);
    for (int it = 0; it < MAX_ITER; ++it) {
        k_urow<<<1024, 256>>>();
        k_vcol<<<64, 1024>>>();
    }
    k_final<<<1024, 256>>>();
    k_reduce<<<1, 256>>>(out);
}

// round 8
// speedup vs baseline: 1.0691x; 1.0691x over previous
#include <cuda_runtime.h>
#include <math.h>

#define NB 4
#define NP 2048
#define ND 64
#define EPS_F 0.1f
#define THRESH_F 0.1f
#define MAX_ITER 50

static __device__ float g_C[(size_t)NB * NP * NP];   // 64 MB cost matrix
static __device__ float g_u[NB * NP];
static __device__ float g_v[NB * NP];
static __device__ float g_errpart[1024];
static __device__ float g_costpart[1024];
static __device__ int   g_done;

__device__ __forceinline__ float inv_eps() { return 1.0f / EPS_F; }

// L2 evict_last via access policy (ptxas on this toolchain rejects the bare
// .L2::evict_last modifier on .v4.f32; the cache_hint form is accepted).
__device__ __forceinline__ unsigned long long mk_el_policy() {
    unsigned long long p;
    asm("createpolicy.fractional.L2::evict_last.b64 %0, 1.0;" : "=l"(p));
    return p;
}
__device__ __forceinline__ float4 ldg_el4(const float4* p, unsigned long long pol) {
    float4 v;
    asm("ld.global.nc.L2::cache_hint.v4.f32 {%0,%1,%2,%3}, [%4], %5;"
        : "=f"(v.x), "=f"(v.y), "=f"(v.z), "=f"(v.w) : "l"(p), "l"(pol));
    return v;
}
__device__ __forceinline__ void stg_el4(float4* p, float4 v, unsigned long long pol) {
    asm volatile("st.global.L2::cache_hint.v4.f32 [%0], {%1,%2,%3,%4}, %5;"
        :: "l"(p), "f"(v.x), "f"(v.y), "f"(v.z), "f"(v.w), "l"(pol) : "memory");
}

// ---------------------------------------------------------------------------
// init: zero u, v; errpart = huge (first-iteration done check must be false)
// ---------------------------------------------------------------------------
__global__ void k_init() {
    int t = blockIdx.x * blockDim.x + threadIdx.x;
    if (t < NB * NP) { g_u[t] = 0.0f; g_v[t] = 0.0f; }
    if (t < 1024) g_errpart[t] = 1.0e30f;
    if (t == 0) g_done = 0;
}

// ---------------------------------------------------------------------------
// C[b][i][j] = ||x_i||^2 + ||y_j||^2 - 2 * <x_i, y_j>
// grid (32, 32, 4), 256 threads, 64x64 output tile per block
// ---------------------------------------------------------------------------
__global__ void k_cost(const float* __restrict__ x, const float* __restrict__ y) {
    __shared__ __align__(16) float xs[ND][68];
    __shared__ __align__(16) float ys[ND][68];
    __shared__ float nx[64], ny[64];

    int b  = blockIdx.z;
    int i0 = blockIdx.y * 64;
    int j0 = blockIdx.x * 64;
    int tid = threadIdx.x;

    const float* xp = x + ((size_t)b * NP + i0) * ND;
    const float* yp = y + ((size_t)b * NP + j0) * ND;

    for (int idx = tid; idx < 64 * ND; idx += 256) {
        int r = idx >> 6;
        int d = idx & 63;
        xs[d][r] = xp[r * ND + d];
        ys[d][r] = yp[r * ND + d];
    }
    __syncthreads();

    if (tid < 64) {
        float s = 0.0f;
        #pragma unroll 16
        for (int d = 0; d < ND; d++) { float v = xs[d][tid]; s = fmaf(v, v, s); }
        nx[tid] = s;
    } else if (tid < 128) {
        int j = tid - 64;
        float s = 0.0f;
        #pragma unroll 16
        for (int d = 0; d < ND; d++) { float v = ys[d][j]; s = fmaf(v, v, s); }
        ny[j] = s;
    }
    __syncthreads();

    int tx = tid & 15, ty = tid >> 4;
    float acc[4][4] = {};
    #pragma unroll 16
    for (int d = 0; d < ND; d++) {
        float4 xr = *(const float4*)&xs[d][ty * 4];
        float4 yr = *(const float4*)&ys[d][tx * 4];
        float xa[4] = {xr.x, xr.y, xr.z, xr.w};
        float ya[4] = {yr.x, yr.y, yr.z, yr.w};
        #pragma unroll
        for (int a = 0; a < 4; a++)
            #pragma unroll
            for (int c = 0; c < 4; c++)
                acc[a][c] = fmaf(xa[a], ya[c], acc[a][c]);
    }

    unsigned long long pol = mk_el_policy();
    #pragma unroll
    for (int a = 0; a < 4; a++) {
        int i = i0 + ty * 4 + a;
        size_t base = ((size_t)b * NP + i) * NP + j0 + tx * 4;
        float4 o;
        o.x = nx[ty * 4 + a] + ny[tx * 4 + 0] - 2.0f * acc[a][0];
        o.y = nx[ty * 4 + a] + ny[tx * 4 + 1] - 2.0f * acc[a][1];
        o.z = nx[ty * 4 + a] + ny[tx * 4 + 2] - 2.0f * acc[a][2];
        o.w = nx[ty * 4 + a] + ny[tx * 4 + 3] - 2.0f * acc[a][3];
        stg_el4((float4*)&g_C[base], o, pol);
    }
}

// ---------------------------------------------------------------------------
// u update: u_new_i = eps*(log_mu - LSE_j((v_j - C_ij)/eps))
// grid 1024 x 256; warp per row; 8 float4 loads in flight.
// Each block ALSO deterministically reduces last iteration's err partials and
// writes g_done (same value from every block -> race-free "done entering step")
// ---------------------------------------------------------------------------
__global__ __launch_bounds__(256) void k_urow() {
    __shared__ __align__(16) float vs[NP];
    __shared__ float red[256];
    __shared__ float werr[8];
    __shared__ int   sdone;

    int tid = threadIdx.x;
    int rowbase = blockIdx.x * 8;
    int b = rowbase >> 11;

    // overlap v-load with err reduction
    for (int j = tid; j < NP; j += 256) vs[j] = g_v[b * NP + j] * inv_eps();
    {
        float e = 0.0f;
        #pragma unroll
        for (int k = 0; k < 4; k++) e += g_errpart[tid + k * 256];
        red[tid] = e;
    }
    __syncthreads();
    #pragma unroll
    for (int st = 128; st; st >>= 1) {
        if (tid < st) red[tid] += red[tid + st];
        __syncthreads();
    }
    if (tid == 0) {
        int d = (red[0] * (1.0f / (float)NB) < THRESH_F) ? 1 : 0;
        sdone = d;
        g_done = d;       // every block writes the identical value
    }
    __syncthreads();
    if (sdone) return;    // frozen: leave u and errpart untouched

    int w = tid >> 5, lane = tid & 31;
    int row = rowbase + w;
    const float4* Cr = (const float4*)(g_C + (size_t)row * NP);
    const float4* vv = (const float4*)vs;
    unsigned long long pol = mk_el_policy();

    float m = -INFINITY, s = 0.0f;
    #pragma unroll 1
    for (int c = 0; c < 2; c++) {
        float a[32];
        #pragma unroll
        for (int k = 0; k < 8; k++) {
            int q = (c * 8 + k) * 32 + lane;
            float4 Cq = ldg_el4(Cr + q, pol);
            float4 vq = vv[q];
            a[k * 4 + 0] = fmaf(Cq.x, -inv_eps(), vq.x);
            a[k * 4 + 1] = fmaf(Cq.y, -inv_eps(), vq.y);
            a[k * 4 + 2] = fmaf(Cq.z, -inv_eps(), vq.z);
            a[k * 4 + 3] = fmaf(Cq.w, -inv_eps(), vq.w);
        }
        float cm = a[0];
        #pragma unroll
        for (int k = 1; k < 32; k++) cm = fmaxf(cm, a[k]);
        float nm = fmaxf(m, cm);
        s *= __expf(m - nm);
        #pragma unroll
        for (int k = 0; k < 32; k++) s += __expf(a[k] - nm);
        m = nm;
    }
    #pragma unroll
    for (int off = 16; off; off >>= 1) {
        float om = __shfl_down_sync(0xffffffffu, m, off);
        float os = __shfl_down_sync(0xffffffffu, s, off);
        float nm = fmaxf(m, om);
        s = s * __expf(m - nm) + os * __expf(om - nm);
        m = nm;
    }
    if (lane == 0) {
        float lse = m + logf(s);
        float lmu = logf(1.0f / (float)NP + 1e-8f);
        float un  = EPS_F * (lmu - lse);
        float uo  = g_u[row];
        g_u[row]  = un;
        werr[w]   = fabsf(un - uo);
    }
    __syncthreads();
    if (tid == 0) {
        float e = 0.0f;
        #pragma unroll
        for (int k = 0; k < 8; k++) e += werr[k];
        g_errpart[blockIdx.x] = e;
    }
}

// ---------------------------------------------------------------------------
// v update: v_new_j = eps*(log_nu - LSE_i((u_i - C_ij)/eps))    (u = new u)
// grid 64 blocks x 1024 threads; block = (b, 128-col tile).
// Lane owns 4 columns (float4 loads, 512B/warp/row); warp w covers rows
// [w*64, w*64+64). Per-warp (m,s) partials combined in smem, v written direct.
// ---------------------------------------------------------------------------
__global__ __launch_bounds__(1024) void k_vcol() {
    if (*(volatile int*)&g_done) return; // value written by this step's k_urow
    __shared__ float us[NP];            // 8KB
    __shared__ float smM[32][128];      // 16KB
    __shared__ float smS[32][128];      // 16KB

    int tid = threadIdx.x;
    int b  = blockIdx.x >> 4;
    int j0 = (blockIdx.x & 15) * 128;

    for (int i = tid; i < NP; i += 1024) us[i] = g_u[b * NP + i] * inv_eps();
    __syncthreads();

    int w = tid >> 5, lane = tid & 31;
    const float4* Cb = (const float4*)(g_C + (size_t)b * NP * NP) + (j0 >> 2) + lane;
    int rbase = w * 64;
    unsigned long long pol = mk_el_policy();

    float4 m4 = make_float4(-INFINITY, -INFINITY, -INFINITY, -INFINITY);
    float4 s4 = make_float4(0.0f, 0.0f, 0.0f, 0.0f);

    #pragma unroll 1
    for (int c = 0; c < 8; c++) {
        float4 a[8];
        int ib = rbase + c * 8;
        #pragma unroll
        for (int k = 0; k < 8; k++) {
            float4 Cq = ldg_el4(Cb + (size_t)(ib + k) * (NP / 4), pol);
            float ui  = us[ib + k];
            a[k].x = fmaf(Cq.x, -inv_eps(), ui);
            a[k].y = fmaf(Cq.y, -inv_eps(), ui);
            a[k].z = fmaf(Cq.z, -inv_eps(), ui);
            a[k].w = fmaf(Cq.w, -inv_eps(), ui);
        }
        #define LSE_COMP(F) { \
            float cm = a[0].F; \
            _Pragma("unroll") \
            for (int k = 1; k < 8; k++) cm = fmaxf(cm, a[k].F); \
            float nm = fmaxf(m4.F, cm); \
            s4.F *= __expf(m4.F - nm); \
            _Pragma("unroll") \
            for (int k = 0; k < 8; k++) s4.F += __expf(a[k].F - nm); \
            m4.F = nm; }
        LSE_COMP(x) LSE_COMP(y) LSE_COMP(z) LSE_COMP(w)
        #undef LSE_COMP
    }

    *(float4*)&smM[w][lane * 4] = m4;
    *(float4*)&smS[w][lane * 4] = s4;
    __syncthreads();

    if (tid < 128) {
        float M = smM[0][tid];
        #pragma unroll
        for (int k = 1; k < 32; k++) M = fmaxf(M, smM[k][tid]);
        float S = 0.0f;
        #pragma unroll
        for (int k = 0; k < 32; k++) S += smS[k][tid] * __expf(smM[k][tid] - M);
        float lse = M + logf(S);
        float lnu = logf(1.0f / (float)NP + 1e-8f);
        g_v[b * NP + j0 + tid] = EPS_F * (lnu - lse);
    }
}

// ---------------------------------------------------------------------------
// final: cost partials  sum_ij exp((u_i + v_j - C)/eps) * C ; float4 loads
// ---------------------------------------------------------------------------
__global__ __launch_bounds__(256) void k_final() {
    __shared__ __align__(16) float vs[NP];
    __shared__ float wsum[8];

    int tid = threadIdx.x;
    int rowbase = blockIdx.x * 8;
    int b = rowbase >> 11;

    for (int j = tid; j < NP; j += 256) vs[j] = g_v[b * NP + j] * inv_eps();
    __syncthreads();

    int w = tid >> 5, lane = tid & 31;
    int row = rowbase + w;
    const float4* Cr = (const float4*)(g_C + (size_t)row * NP);
    const float4* vv = (const float4*)vs;
    float uie = g_u[row] * inv_eps();
    unsigned long long pol = mk_el_policy();

    float acc = 0.0f;
    #pragma unroll 4
    for (int t = 0; t < 16; t++) {
        int q = t * 32 + lane;
        float4 Cq = ldg_el4(Cr + q, pol);
        float4 vq = vv[q];
        float e0 = __expf(fmaf(Cq.x, -inv_eps(), uie + vq.x));
        float e1 = __expf(fmaf(Cq.y, -inv_eps(), uie + vq.y));
        float e2 = __expf(fmaf(Cq.z, -inv_eps(), uie + vq.z));
        float e3 = __expf(fmaf(Cq.w, -inv_eps(), uie + vq.w));
        acc = fmaf(e0, Cq.x, acc);
        acc = fmaf(e1, Cq.y, acc);
        acc = fmaf(e2, Cq.z, acc);
        acc = fmaf(e3, Cq.w, acc);
    }
    #pragma unroll
    for (int off = 16; off; off >>= 1)
        acc += __shfl_down_sync(0xffffffffu, acc, off);
    if (lane == 0) wsum[w] = acc;
    __syncthreads();
    if (tid == 0) {
        float e = 0.0f;
        #pragma unroll
        for (int k = 0; k < 8; k++) e += wsum[k];
        g_costpart[blockIdx.x] = e;
    }
}

__global__ void k_reduce(float* out) {
    __shared__ float red[256];
    int tid = threadIdx.x;
    float e = 0.0f;
    for (int k = tid; k < 1024; k += 256) e += g_costpart[k];
    red[tid] = e;
    __syncthreads();
    for (int st = 128; st; st >>= 1) {
        if (tid < st) red[tid] += red[tid + st];
        __syncthreads();
    }
    if (tid == 0) out[0] = red[0] * (1.0f / (float)NB);
}

// ---------------------------------------------------------------------------
extern "C" void kernel_launch(void* const* d_in, const int* in_sizes, int n_in,
                              void* d_out, int out_size) {
    const float* x = (const float*)d_in[0];
    const float* y = (const float*)d_in[1];
    float* out = (float*)d_out;

    k_init<<<32, 256>>>();
    dim3 gc(32, 32, 4);
    k_cost<<<gc, 256>>>(x, y);
    for (int it = 0; it < MAX_ITER; ++it) {
        k_urow<<<1024, 256>>>();
        k_vcol<<<64, 1024>>>();
    }
    k_final<<<1024, 256>>>();
    k_reduce<<<1, 256>>>(out);
}

// round 9
// speedup vs baseline: 1.1192x; 1.0469x over previous
#include <cuda_runtime.h>
#include <cuda_fp16.h>
#include <math.h>
#include <string.h>

#define NB 4
#define NP 2048
#define ND 64
#define EPS_F 0.1f
#define IEPS 10.0f
#define THRESH_F 0.1f
#define MAX_ITER 50

// D[b][i][j] = 2 * <x_bi, y_bj>  stored fp16 (32 MB). All sweeps touch only D.
static __device__ __half g_D[(size_t)NB * NP * NP];
static __device__ float g_nx[NB * NP], g_ny[NB * NP];
static __device__ float g_p[NB * NP];                  // p = u - nx
static __device__ float g_qm[2][NB * NP];              // col-pass partials (max)
static __device__ float g_qs[2][NB * NP];              // col-pass partials (sum)
static __device__ float g_errpart[1024];
static __device__ float g_costpart[1024];
static __device__ int   g_done;

__device__ __forceinline__ unsigned long long mk_el_policy() {
    unsigned long long p;
    asm("createpolicy.fractional.L2::evict_last.b64 %0, 1.0;" : "=l"(p));
    return p;
}
__device__ __forceinline__ uint4 ldg_el4u(const uint4* p, unsigned long long pol) {
    uint4 v;
    asm("ld.global.nc.L2::cache_hint.v4.u32 {%0,%1,%2,%3}, [%4], %5;"
        : "=r"(v.x), "=r"(v.y), "=r"(v.z), "=r"(v.w) : "l"(p), "l"(pol));
    return v;
}
__device__ __forceinline__ uint2 ldg_el2u(const uint2* p, unsigned long long pol) {
    uint2 v;
    asm("ld.global.nc.L2::cache_hint.v2.u32 {%0,%1}, [%2], %3;"
        : "=r"(v.x), "=r"(v.y) : "l"(p), "l"(pol));
    return v;
}
__device__ __forceinline__ void stg_el2u(uint2* p, uint2 v, unsigned long long pol) {
    asm volatile("st.global.L2::cache_hint.v2.u32 [%0], {%1,%2}, %3;"
        :: "l"(p), "r"(v.x), "r"(v.y), "l"(pol) : "memory");
}
__device__ __forceinline__ float2 h2f(unsigned u) {
    __half2 h; memcpy(&h, &u, 4);
    return __half22float2(h);
}

// ---------------------------------------------------------------------------
// nx/ny: squared norms. warp per row; 16384 rows (x then y).
// ---------------------------------------------------------------------------
__global__ __launch_bounds__(256) void k_nxny(const float* __restrict__ x,
                                              const float* __restrict__ y) {
    int gw   = (blockIdx.x * 256 + threadIdx.x) >> 5;
    int lane = threadIdx.x & 31;
    const float* src = (gw < NB * NP) ? x + (size_t)gw * ND
                                      : y + (size_t)(gw - NB * NP) * ND;
    float2 v = ((const float2*)src)[lane];
    float s = v.x * v.x + v.y * v.y;
    #pragma unroll
    for (int off = 16; off; off >>= 1)
        s += __shfl_down_sync(0xffffffffu, s, off);
    if (lane == 0) {
        if (gw < NB * NP) g_nx[gw] = s;
        else              g_ny[gw - NB * NP] = s;
    }
}

// ---------------------------------------------------------------------------
// init: p = -nx (u=0); q partials encode q = -ny (v=0); errpart huge.
// Runs AFTER k_nxny.
// ---------------------------------------------------------------------------
__global__ void k_init() {
    int t = blockIdx.x * blockDim.x + threadIdx.x;
    float lnu = logf(1.0f / (float)NP + 1e-8f);
    if (t < NB * NP) {
        g_p[t] = -g_nx[t];
        float m = lnu + g_ny[t] * IEPS;   // lnu - (m + log(0.5+0.5)) = -ny/eps
        g_qm[0][t] = m;  g_qm[1][t] = m;
        g_qs[0][t] = 0.5f; g_qs[1][t] = 0.5f;
    }
    if (t < 1024) g_errpart[t] = 1.0e30f;
    if (t == 0) g_done = 0;
}

// ---------------------------------------------------------------------------
// D = 2<x,y>, fp16.  grid (32,32,4), 256 thr, 64x64 tile.
// ---------------------------------------------------------------------------
__global__ __launch_bounds__(256) void k_costd(const float* __restrict__ x,
                                               const float* __restrict__ y) {
    __shared__ __align__(16) float xs[ND][68];
    __shared__ __align__(16) float ys[ND][68];

    int b  = blockIdx.z;
    int i0 = blockIdx.y * 64;
    int j0 = blockIdx.x * 64;
    int tid = threadIdx.x;

    const float* xp = x + ((size_t)b * NP + i0) * ND;
    const float* yp = y + ((size_t)b * NP + j0) * ND;

    for (int idx = tid; idx < 64 * ND; idx += 256) {
        int r = idx >> 6;
        int d = idx & 63;
        xs[d][r] = xp[r * ND + d];
        ys[d][r] = yp[r * ND + d];
    }
    __syncthreads();

    int tx = tid & 15, ty = tid >> 4;
    float acc[4][4] = {};
    #pragma unroll 16
    for (int d = 0; d < ND; d++) {
        float4 xr = *(const float4*)&xs[d][ty * 4];
        float4 yr = *(const float4*)&ys[d][tx * 4];
        float xa[4] = {xr.x, xr.y, xr.z, xr.w};
        float ya[4] = {yr.x, yr.y, yr.z, yr.w};
        #pragma unroll
        for (int a = 0; a < 4; a++)
            #pragma unroll
            for (int c = 0; c < 4; c++)
                acc[a][c] = fmaf(xa[a], ya[c], acc[a][c]);
    }

    unsigned long long pol = mk_el_policy();
    #pragma unroll
    for (int a = 0; a < 4; a++) {
        int i = i0 + ty * 4 + a;
        size_t base = ((size_t)b * NP + i) * NP + j0 + tx * 4;
        __half2 h01 = __floats2half2_rn(2.0f * acc[a][0], 2.0f * acc[a][1]);
        __half2 h23 = __floats2half2_rn(2.0f * acc[a][2], 2.0f * acc[a][3]);
        uint2 o;
        memcpy(&o.x, &h01, 4);
        memcpy(&o.y, &h23, 4);
        stg_el2u((uint2*)(g_D + base), o, pol);
    }
}

// ---------------------------------------------------------------------------
// row pass: p_new_i = eps*(lmu - LSE_j(qs_j + 10*D_ij)), qs = q/eps from
// the 2 column partials. Also reduces last iteration's err -> g_done.
// grid 1024 x 256; warp per row.
// ---------------------------------------------------------------------------
__global__ __launch_bounds__(256) void k_prow() {
    __shared__ __align__(16) float qs[NP];
    __shared__ float red[256];
    __shared__ float werr[8];
    __shared__ int   sdone;

    int tid = threadIdx.x;
    int rowbase = blockIdx.x * 8;
    int b = rowbase >> 11;
    float lnu = logf(1.0f / (float)NP + 1e-8f);

    // reconstruct q/eps from partials (L2-hot, 32KB/block)
    for (int j = tid; j < NP; j += 256) {
        int col = b * NP + j;
        float m0 = g_qm[0][col], m1 = g_qm[1][col];
        float M  = fmaxf(m0, m1);
        float S  = g_qs[0][col] * __expf(m0 - M) + g_qs[1][col] * __expf(m1 - M);
        qs[j] = lnu - (M + logf(S));
    }
    {
        float e = 0.0f;
        #pragma unroll
        for (int k = 0; k < 4; k++) e += g_errpart[tid + k * 256];
        red[tid] = e;
    }
    __syncthreads();
    #pragma unroll
    for (int st = 128; st; st >>= 1) {
        if (tid < st) red[tid] += red[tid + st];
        __syncthreads();
    }
    if (tid == 0) {
        int d = (red[0] * (1.0f / (float)NB) < THRESH_F) ? 1 : 0;
        sdone = d;
        g_done = d;
    }
    __syncthreads();
    if (sdone) return;

    int w = tid >> 5, lane = tid & 31;
    int row = rowbase + w;
    const uint4* Dr = (const uint4*)(g_D + (size_t)row * NP);  // 256 uint4/row
    const float4* qv = (const float4*)qs;
    unsigned long long pol = mk_el_policy();

    float m = -INFINITY, s = 0.0f;
    #pragma unroll 1
    for (int c = 0; c < 2; c++) {
        uint4 L[4];
        #pragma unroll
        for (int k = 0; k < 4; k++)
            L[k] = ldg_el4u(Dr + (c * 4 + k) * 32 + lane, pol);
        float a[32];
        #pragma unroll
        for (int k = 0; k < 4; k++) {
            int q = (c * 4 + k) * 32 + lane;     // chunk of 8 halves
            float4 q0 = qv[q * 2];
            float4 q1 = qv[q * 2 + 1];
            float2 f0 = h2f(L[k].x), f1 = h2f(L[k].y);
            float2 f2 = h2f(L[k].z), f3 = h2f(L[k].w);
            a[k*8+0] = fmaf(f0.x, IEPS, q0.x);
            a[k*8+1] = fmaf(f0.y, IEPS, q0.y);
            a[k*8+2] = fmaf(f1.x, IEPS, q0.z);
            a[k*8+3] = fmaf(f1.y, IEPS, q0.w);
            a[k*8+4] = fmaf(f2.x, IEPS, q1.x);
            a[k*8+5] = fmaf(f2.y, IEPS, q1.y);
            a[k*8+6] = fmaf(f3.x, IEPS, q1.z);
            a[k*8+7] = fmaf(f3.y, IEPS, q1.w);
        }
        float cm = a[0];
        #pragma unroll
        for (int k = 1; k < 32; k++) cm = fmaxf(cm, a[k]);
        float nm = fmaxf(m, cm);
        s *= __expf(m - nm);
        #pragma unroll
        for (int k = 0; k < 32; k++) s += __expf(a[k] - nm);
        m = nm;
    }
    #pragma unroll
    for (int off = 16; off; off >>= 1) {
        float om = __shfl_down_sync(0xffffffffu, m, off);
        float os = __shfl_down_sync(0xffffffffu, s, off);
        float nm = fmaxf(m, om);
        s = s * __expf(m - nm) + os * __expf(om - nm);
        m = nm;
    }
    if (lane == 0) {
        float lse = m + logf(s);
        float lmu = logf(1.0f / (float)NP + 1e-8f);
        float pn  = EPS_F * (lmu - lse);
        float po  = g_p[row];
        g_p[row]  = pn;
        werr[w]   = fabsf(pn - po);
    }
    __syncthreads();
    if (tid == 0) {
        float e = 0.0f;
        #pragma unroll
        for (int k = 0; k < 8; k++) e += werr[k];
        g_errpart[blockIdx.x] = e;
    }
}

// ---------------------------------------------------------------------------
// col pass: LSE_i(ps_i + 10*D_ij) partials. grid 128 x 1024:
// block = (b, 128-col tile, row-half). lane owns 4 cols (uint2 = 8B loads),
// warp covers 32 rows of its half; 32-warp smem combine -> (m,s) partial.
// ---------------------------------------------------------------------------
__global__ __launch_bounds__(1024) void k_qcol() {
    if (*(volatile int*)&g_done) return;
    __shared__ float ps[NP];
    __shared__ float smM[32][128];
    __shared__ float smS[32][128];

    int tid   = threadIdx.x;
    int bid   = blockIdx.x;
    int split = bid & 1;
    int tile  = (bid >> 1) & 15;
    int b     = bid >> 5;

    for (int i = tid; i < NP; i += 1024) ps[i] = g_p[b * NP + i] * IEPS;
    __syncthreads();

    int w = tid >> 5, lane = tid & 31;
    int r0 = split * 1024 + w * 32;
    const uint2* Db = (const uint2*)(g_D + (size_t)b * NP * NP + tile * 128) + lane;
    unsigned long long pol = mk_el_policy();

    float4 m4 = make_float4(-INFINITY, -INFINITY, -INFINITY, -INFINITY);
    float4 s4 = make_float4(0.0f, 0.0f, 0.0f, 0.0f);

    #pragma unroll 1
    for (int c = 0; c < 4; c++) {
        uint2 L[8];
        int rb = r0 + c * 8;
        #pragma unroll
        for (int k = 0; k < 8; k++)
            L[k] = ldg_el2u(Db + (size_t)(rb + k) * (NP / 4), pol);
        float ax[8], ay[8];
        // first half2 of each row: cols lane*4 + {0,1}
        #pragma unroll
        for (int k = 0; k < 8; k++) {
            float2 f = h2f(L[k].x);
            float pi = ps[rb + k];
            ax[k] = fmaf(f.x, IEPS, pi);
            ay[k] = fmaf(f.y, IEPS, pi);
        }
        #define LSE8(arr, MF, SF) { \
            float cm = arr[0]; \
            _Pragma("unroll") \
            for (int k = 1; k < 8; k++) cm = fmaxf(cm, arr[k]); \
            float nm = fmaxf(MF, cm); \
            SF *= __expf(MF - nm); \
            _Pragma("unroll") \
            for (int k = 0; k < 8; k++) SF += __expf(arr[k] - nm); \
            MF = nm; }
        LSE8(ax, m4.x, s4.x)
        LSE8(ay, m4.y, s4.y)
        // second half2: cols lane*4 + {2,3}
        #pragma unroll
        for (int k = 0; k < 8; k++) {
            float2 f = h2f(L[k].y);
            float pi = ps[rb + k];
            ax[k] = fmaf(f.x, IEPS, pi);
            ay[k] = fmaf(f.y, IEPS, pi);
        }
        LSE8(ax, m4.z, s4.z)
        LSE8(ay, m4.w, s4.w)
        #undef LSE8
    }

    *(float4*)&smM[w][lane * 4] = m4;
    *(float4*)&smS[w][lane * 4] = s4;
    __syncthreads();

    if (tid < 128) {
        float M = smM[0][tid];
        #pragma unroll
        for (int k = 1; k < 32; k++) M = fmaxf(M, smM[k][tid]);
        float S = 0.0f;
        #pragma unroll
        for (int k = 0; k < 32; k++) S += smS[k][tid] * __expf(smM[k][tid] - M);
        int col = b * NP + tile * 128 + tid;
        g_qm[split][col] = M;
        g_qs[split][col] = S;
    }
}

// ---------------------------------------------------------------------------
// final: cost = sum_ij exp(pe_i + qs_j + 10*D) * (nx_i + ny_j - D)
// ---------------------------------------------------------------------------
__global__ __launch_bounds__(256) void k_final() {
    __shared__ __align__(16) float qs[NP];
    __shared__ __align__(16) float nys[NP];
    __shared__ float wsum[8];

    int tid = threadIdx.x;
    int rowbase = blockIdx.x * 8;
    int b = rowbase >> 11;
    float lnu = logf(1.0f / (float)NP + 1e-8f);

    for (int j = tid; j < NP; j += 256) {
        int col = b * NP + j;
        float m0 = g_qm[0][col], m1 = g_qm[1][col];
        float M  = fmaxf(m0, m1);
        float S  = g_qs[0][col] * __expf(m0 - M) + g_qs[1][col] * __expf(m1 - M);
        qs[j]  = lnu - (M + logf(S));
        nys[j] = g_ny[col];
    }
    __syncthreads();

    int w = tid >> 5, lane = tid & 31;
    int row = rowbase + w;
    const uint4* Dr = (const uint4*)(g_D + (size_t)row * NP);
    float pe = g_p[row] * IEPS;
    float nx = g_nx[row];
    unsigned long long pol = mk_el_policy();

    float acc = 0.0f;
    #pragma unroll 1
    for (int c = 0; c < 8; c++) {
        uint4 L = ldg_el4u(Dr + c * 32 + lane, pol);
        int jb = (c * 32 + lane) * 8;
        float2 f[4] = {h2f(L.x), h2f(L.y), h2f(L.z), h2f(L.w)};
        #pragma unroll
        for (int k = 0; k < 4; k++) {
            float d0 = f[k].x, d1 = f[k].y;
            int j0 = jb + k * 2;
            float e0 = __expf(pe + qs[j0]     + d0 * IEPS);
            float e1 = __expf(pe + qs[j0 + 1] + d1 * IEPS);
            acc = fmaf(e0, nx + nys[j0]     - d0, acc);
            acc = fmaf(e1, nx + nys[j0 + 1] - d1, acc);
        }
    }
    #pragma unroll
    for (int off = 16; off; off >>= 1)
        acc += __shfl_down_sync(0xffffffffu, acc, off);
    if (lane == 0) wsum[w] = acc;
    __syncthreads();
    if (tid == 0) {
        float e = 0.0f;
        #pragma unroll
        for (int k = 0; k < 8; k++) e += wsum[k];
        g_costpart[blockIdx.x] = e;
    }
}

__global__ void k_reduce(float* out) {
    __shared__ float red[256];
    int tid = threadIdx.x;
    float e = 0.0f;
    for (int k = tid; k < 1024; k += 256) e += g_costpart[k];
    red[tid] = e;
    __syncthreads();
    for (int st = 128; st; st >>= 1) {
        if (tid < st) red[tid] += red[tid + st];
        __syncthreads();
    }
    if (tid == 0) out[0] = red[0] * (1.0f / (float)NB);
}

// ---------------------------------------------------------------------------
extern "C" void kernel_launch(void* const* d_in, const int* in_sizes, int n_in,
                              void* d_out, int out_size) {
    const float* x = (const float*)d_in[0];
    const float* y = (const float*)d_in[1];
    float* out = (float*)d_out;

    k_nxny<<<2048, 256>>>(x, y);
    k_init<<<32, 256>>>();
    dim3 gc(32, 32, 4);
    k_costd<<<gc, 256>>>(x, y);
    for (int it = 0; it < MAX_ITER; ++it) {
        k_prow<<<1024, 256>>>();
        k_qcol<<<128, 1024>>>();
    }
    k_final<<<1024, 256>>>();
    k_reduce<<<1, 256>>>(out);
}

// round 10
// speedup vs baseline: 1.6368x; 1.4625x over previous
#include <cuda_runtime.h>
#include <cuda_fp16.h>
#include <math.h>
#include <string.h>

#define NB 4
#define NP 2048
#define ND 64
#define EPS_F 0.1f
#define IEPS 10.0f
#define THRESH_F 0.1f
#define MAX_ITER 50
#define SKIP_T 22.0f
#define LMU (-7.6245985f)   // log(1/2048 + 1e-8)

// D[b][i][j] = 2 * <x_bi, y_bj>  fp16 (32 MB). All sweeps touch only D.
static __device__ __half g_D[(size_t)NB * NP * NP];
static __device__ float g_nx[NB * NP], g_ny[NB * NP];
static __device__ float g_p[NB * NP];          // p = (u - nx)/eps
static __device__ float g_q[NB * NP];          // q = (v - ny)/eps
static __device__ float g_qm[2][NB * NP];      // col-pass partial max
static __device__ float g_qs[2][NB * NP];      // col-pass partial sum
static __device__ float g_errpart[1024];
static __device__ float g_costpart[1024];
static __device__ int   g_done;

__device__ __forceinline__ float2 h2f(unsigned u) {
    __half2 h; memcpy(&h, &u, 4);
    return __half22float2(h);
}

// ---------------------------------------------------------------------------
// squared norms; warp per row, 16384 warps (x then y)
// ---------------------------------------------------------------------------
__global__ __launch_bounds__(256) void k_nxny(const float* __restrict__ x,
                                              const float* __restrict__ y) {
    int gw   = (blockIdx.x * 256 + threadIdx.x) >> 5;
    int lane = threadIdx.x & 31;
    const float* src = (gw < NB * NP) ? x + (size_t)gw * ND
                                      : y + (size_t)(gw - NB * NP) * ND;
    float2 v = ((const float2*)src)[lane];
    float s = v.x * v.x + v.y * v.y;
    #pragma unroll
    for (int off = 16; off; off >>= 1)
        s += __shfl_down_sync(0xffffffffu, s, off);
    if (lane == 0) {
        if (gw < NB * NP) g_nx[gw] = s;
        else              g_ny[gw - NB * NP] = s;
    }
}

// init (after k_nxny): u=v=0  ->  p = -10*nx, q = -10*ny
__global__ void k_init() {
    int t = blockIdx.x * blockDim.x + threadIdx.x;
    if (t < NB * NP) {
        g_p[t] = -IEPS * g_nx[t];
        g_q[t] = -IEPS * g_ny[t];
    }
    if (t == 0) g_done = 0;
}

// ---------------------------------------------------------------------------
// D = 2<x,y> fp16; grid (32,32,4), 256 thr, 64x64 tile
// ---------------------------------------------------------------------------
__global__ __launch_bounds__(256) void k_costd(const float* __restrict__ x,
                                               const float* __restrict__ y) {
    __shared__ __align__(16) float xs[ND][68];
    __shared__ __align__(16) float ys[ND][68];

    int b  = blockIdx.z;
    int i0 = blockIdx.y * 64;
    int j0 = blockIdx.x * 64;
    int tid = threadIdx.x;

    const float* xp = x + ((size_t)b * NP + i0) * ND;
    const float* yp = y + ((size_t)b * NP + j0) * ND;

    for (int idx = tid; idx < 64 * ND; idx += 256) {
        int r = idx >> 6;
        int d = idx & 63;
        xs[d][r] = xp[r * ND + d];
        ys[d][r] = yp[r * ND + d];
    }
    __syncthreads();

    int tx = tid & 15, ty = tid >> 4;
    float acc[4][4] = {};
    #pragma unroll 16
    for (int d = 0; d < ND; d++) {
        float4 xr = *(const float4*)&xs[d][ty * 4];
        float4 yr = *(const float4*)&ys[d][tx * 4];
        float xa[4] = {xr.x, xr.y, xr.z, xr.w};
        float ya[4] = {yr.x, yr.y, yr.z, yr.w};
        #pragma unroll
        for (int a = 0; a < 4; a++)
            #pragma unroll
            for (int c = 0; c < 4; c++)
                acc[a][c] = fmaf(xa[a], ya[c], acc[a][c]);
    }

    #pragma unroll
    for (int a = 0; a < 4; a++) {
        int i = i0 + ty * 4 + a;
        size_t base = ((size_t)b * NP + i) * NP + j0 + tx * 4;
        __half2 h01 = __floats2half2_rn(2.0f * acc[a][0], 2.0f * acc[a][1]);
        __half2 h23 = __floats2half2_rn(2.0f * acc[a][2], 2.0f * acc[a][3]);
        uint2 o;
        memcpy(&o.x, &h01, 4);
        memcpy(&o.y, &h23, 4);
        *(uint2*)(g_D + base) = o;
    }
}

// ---------------------------------------------------------------------------
// row pass: p_new_i = LMU - LSE_j(q_j + 10*D_ij)
// grid 1024 x 256, warp/row. Two-pass per row: exact max (FMA only), then
// exp only on 256-element stripes within SKIP_T of the row max.
// ---------------------------------------------------------------------------
__global__ __launch_bounds__(256) void k_prow() {
    if (*(volatile int*)&g_done) return;
    __shared__ __align__(16) float qs[NP];
    __shared__ float werr[8];

    int tid = threadIdx.x;
    int rowbase = blockIdx.x * 8;
    int b = rowbase >> 11;

    {   // coalesced 8KB q load
        const float4* src = (const float4*)(g_q + b * NP);
        float4* dst = (float4*)qs;
        #pragma unroll
        for (int k = 0; k < 2; k++) dst[tid + k * 256] = src[tid + k * 256];
    }
    __syncthreads();

    int w = tid >> 5, lane = tid & 31;
    int row = rowbase + w;
    const uint4* Dr = (const uint4*)(g_D + (size_t)row * NP);
    const float4* qv = (const float4*)qs;

    uint4 L[8];
    #pragma unroll
    for (int k = 0; k < 8; k++) L[k] = __ldg(Dr + k * 32 + lane);

    // pass A: chunk maxes (8 values per chunk), row max
    float cm[8];
    float m = -INFINITY;
    #pragma unroll
    for (int k = 0; k < 8; k++) {
        int qi = (k * 32 + lane) * 2;
        float4 q0 = qv[qi], q1 = qv[qi + 1];
        float2 f0 = h2f(L[k].x), f1 = h2f(L[k].y);
        float2 f2 = h2f(L[k].z), f3 = h2f(L[k].w);
        float a0 = fmaf(f0.x, IEPS, q0.x);
        float a1 = fmaf(f0.y, IEPS, q0.y);
        float a2 = fmaf(f1.x, IEPS, q0.z);
        float a3 = fmaf(f1.y, IEPS, q0.w);
        float a4 = fmaf(f2.x, IEPS, q1.x);
        float a5 = fmaf(f2.y, IEPS, q1.y);
        float a6 = fmaf(f3.x, IEPS, q1.z);
        float a7 = fmaf(f3.y, IEPS, q1.w);
        float c01 = fmaxf(fmaxf(a0, a1), fmaxf(a2, a3));
        float c23 = fmaxf(fmaxf(a4, a5), fmaxf(a6, a7));
        cm[k] = fmaxf(c01, c23);
        m = fmaxf(m, cm[k]);
    }
    #pragma unroll
    for (int off = 16; off; off >>= 1)
        m = fmaxf(m, __shfl_xor_sync(0xffffffffu, m, off));

    // pass B: selective exp
    float s = 0.0f;
    float thr = m - SKIP_T;
    #pragma unroll
    for (int k = 0; k < 8; k++) {
        if (__any_sync(0xffffffffu, cm[k] > thr)) {
            int qi = (k * 32 + lane) * 2;
            float4 q0 = qv[qi], q1 = qv[qi + 1];
            float2 f0 = h2f(L[k].x), f1 = h2f(L[k].y);
            float2 f2 = h2f(L[k].z), f3 = h2f(L[k].w);
            s += __expf(fmaf(f0.x, IEPS, q0.x) - m);
            s += __expf(fmaf(f0.y, IEPS, q0.y) - m);
            s += __expf(fmaf(f1.x, IEPS, q0.z) - m);
            s += __expf(fmaf(f1.y, IEPS, q0.w) - m);
            s += __expf(fmaf(f2.x, IEPS, q1.x) - m);
            s += __expf(fmaf(f2.y, IEPS, q1.y) - m);
            s += __expf(fmaf(f3.x, IEPS, q1.z) - m);
            s += __expf(fmaf(f3.y, IEPS, q1.w) - m);
        }
    }
    #pragma unroll
    for (int off = 16; off; off >>= 1)
        s += __shfl_xor_sync(0xffffffffu, s, off);

    if (lane == 0) {
        float pn = LMU - (m + __logf(s));
        float po = g_p[row];
        g_p[row] = pn;
        werr[w]  = EPS_F * fabsf(pn - po);   // |u_new - u_old|
    }
    __syncthreads();
    if (tid == 0) {
        float e = 0.0f;
        #pragma unroll
        for (int k = 0; k < 8; k++) e += werr[k];
        g_errpart[blockIdx.x] = e;
    }
}

// ---------------------------------------------------------------------------
// col pass partials: LSE_i(p_i + 10*D_ij) over 1024-row halves.
// grid 128 x 1024: block = (b, 128-col tile, split). lane owns 4 cols;
// warp covers 32 rows; group-max skip avoids exp on negligible 8-row groups.
// ---------------------------------------------------------------------------
__global__ __launch_bounds__(1024) void k_qcol() {
    if (*(volatile int*)&g_done) return;
    __shared__ float ps[NP];
    __shared__ float smM[32][128];
    __shared__ float smS[32][128];

    int tid   = threadIdx.x;
    int bid   = blockIdx.x;
    int split = bid & 1;
    int tile  = (bid >> 1) & 15;
    int b     = bid >> 5;

    for (int i = tid; i < NP; i += 1024) ps[i] = g_p[b * NP + i];
    __syncthreads();

    int w = tid >> 5, lane = tid & 31;
    int r0 = split * 1024 + w * 32;
    const uint2* Db = (const uint2*)(g_D + (size_t)b * NP * NP + tile * 128) + lane;

    float4 m4 = make_float4(-INFINITY, -INFINITY, -INFINITY, -INFINITY);
    float4 s4 = make_float4(0.0f, 0.0f, 0.0f, 0.0f);

    #pragma unroll 1
    for (int c = 0; c < 4; c++) {
        uint2 Lr[8];
        int rb = r0 + c * 8;
        #pragma unroll
        for (int k = 0; k < 8; k++)
            Lr[k] = __ldg(Db + (size_t)(rb + k) * (NP / 4));
        float pv[8];
        #pragma unroll
        for (int k = 0; k < 8; k++) pv[k] = ps[rb + k];

        float ax[8], ay[8];
        // half2 0: cols lane*4 + {0,1}
        #pragma unroll
        for (int k = 0; k < 8; k++) {
            float2 f = h2f(Lr[k].x);
            ax[k] = fmaf(f.x, IEPS, pv[k]);
            ay[k] = fmaf(f.y, IEPS, pv[k]);
        }
        {
            float gx = ax[0], gy = ay[0];
            #pragma unroll
            for (int k = 1; k < 8; k++) { gx = fmaxf(gx, ax[k]); gy = fmaxf(gy, ay[k]); }
            if (__any_sync(0xffffffffu,
                           (gx > m4.x - SKIP_T) | (gy > m4.y - SKIP_T))) {
                float nm = fmaxf(m4.x, gx);
                s4.x *= __expf(m4.x - nm);
                #pragma unroll
                for (int k = 0; k < 8; k++) s4.x += __expf(ax[k] - nm);
                m4.x = nm;
                nm = fmaxf(m4.y, gy);
                s4.y *= __expf(m4.y - nm);
                #pragma unroll
                for (int k = 0; k < 8; k++) s4.y += __expf(ay[k] - nm);
                m4.y = nm;
            }
        }
        // half2 1: cols lane*4 + {2,3}
        #pragma unroll
        for (int k = 0; k < 8; k++) {
            float2 f = h2f(Lr[k].y);
            ax[k] = fmaf(f.x, IEPS, pv[k]);
            ay[k] = fmaf(f.y, IEPS, pv[k]);
        }
        {
            float gx = ax[0], gy = ay[0];
            #pragma unroll
            for (int k = 1; k < 8; k++) { gx = fmaxf(gx, ax[k]); gy = fmaxf(gy, ay[k]); }
            if (__any_sync(0xffffffffu,
                           (gx > m4.z - SKIP_T) | (gy > m4.w - SKIP_T))) {
                float nm = fmaxf(m4.z, gx);
                s4.z *= __expf(m4.z - nm);
                #pragma unroll
                for (int k = 0; k < 8; k++) s4.z += __expf(ax[k] - nm);
                m4.z = nm;
                nm = fmaxf(m4.w, gy);
                s4.w *= __expf(m4.w - nm);
                #pragma unroll
                for (int k = 0; k < 8; k++) s4.w += __expf(ay[k] - nm);
                m4.w = nm;
            }
        }
    }

    *(float4*)&smM[w][lane * 4] = m4;
    *(float4*)&smS[w][lane * 4] = s4;
    __syncthreads();

    if (tid < 128) {
        float M = smM[0][tid];
        #pragma unroll
        for (int k = 1; k < 32; k++) M = fmaxf(M, smM[k][tid]);
        float S = 0.0f;
        #pragma unroll
        for (int k = 0; k < 32; k++) S += smS[k][tid] * __expf(smM[k][tid] - M);
        int col = b * NP + tile * 128 + tid;
        g_qm[split][col] = M;
        g_qs[split][col] = S;
    }
}

// ---------------------------------------------------------------------------
// finalize: q_j = LMU - LSE over both splits; block 0 reduces err -> g_done
// ---------------------------------------------------------------------------
__global__ __launch_bounds__(512) void k_qfin() {
    if (*(volatile int*)&g_done) return;
    int t = blockIdx.x * 512 + threadIdx.x;        // 0..8191
    float m0 = g_qm[0][t], m1 = g_qm[1][t];
    float M  = fmaxf(m0, m1);
    float S  = g_qs[0][t] * __expf(m0 - M) + g_qs[1][t] * __expf(m1 - M);
    g_q[t] = LMU - (M + __logf(S));

    if (blockIdx.x == 0) {
        __shared__ float red[512];
        int tid = threadIdx.x;
        red[tid] = g_errpart[tid] + g_errpart[tid + 512];
        __syncthreads();
        #pragma unroll
        for (int st = 256; st; st >>= 1) {
            if (tid < st) red[tid] += red[tid + st];
            __syncthreads();
        }
        if (tid == 0)
            g_done = (red[0] * (1.0f / (float)NB) < THRESH_F) ? 1 : 0;
    }
}

// ---------------------------------------------------------------------------
// final: cost = sum_ij exp(p_i + q_j + 10D) * (nx_i + ny_j - D)
// ---------------------------------------------------------------------------
__global__ __launch_bounds__(256) void k_final() {
    __shared__ __align__(16) float qs[NP];
    __shared__ __align__(16) float nys[NP];
    __shared__ float wsum[8];

    int tid = threadIdx.x;
    int rowbase = blockIdx.x * 8;
    int b = rowbase >> 11;

    for (int j = tid; j < NP; j += 256) {
        qs[j]  = g_q[b * NP + j];
        nys[j] = g_ny[b * NP + j];
    }
    __syncthreads();

    int w = tid >> 5, lane = tid & 31;
    int row = rowbase + w;
    const uint4* Dr = (const uint4*)(g_D + (size_t)row * NP);
    float pe = g_p[row];
    float nx = g_nx[row];

    float acc = 0.0f;
    #pragma unroll 1
    for (int c = 0; c < 8; c++) {
        uint4 L = __ldg(Dr + c * 32 + lane);
        int jb = (c * 32 + lane) * 8;
        float2 f[4] = {h2f(L.x), h2f(L.y), h2f(L.z), h2f(L.w)};
        #pragma unroll
        for (int k = 0; k < 4; k++) {
            float d0 = f[k].x, d1 = f[k].y;
            int j0 = jb + k * 2;
            float e0 = __expf(pe + qs[j0]     + d0 * IEPS);
            float e1 = __expf(pe + qs[j0 + 1] + d1 * IEPS);
            acc = fmaf(e0, nx + nys[j0]     - d0, acc);
            acc = fmaf(e1, nx + nys[j0 + 1] - d1, acc);
        }
    }
    #pragma unroll
    for (int off = 16; off; off >>= 1)
        acc += __shfl_down_sync(0xffffffffu, acc, off);
    if (lane == 0) wsum[w] = acc;
    __syncthreads();
    if (tid == 0) {
        float e = 0.0f;
        #pragma unroll
        for (int k = 0; k < 8; k++) e += wsum[k];
        g_costpart[blockIdx.x] = e;
    }
}

__global__ void k_reduce(float* out) {
    __shared__ float red[256];
    int tid = threadIdx.x;
    float e = 0.0f;
    for (int k = tid; k < 1024; k += 256) e += g_costpart[k];
    red[tid] = e;
    __syncthreads();
    for (int st = 128; st; st >>= 1) {
        if (tid < st) red[tid] += red[tid + st];
        __syncthreads();
    }
    if (tid == 0) out[0] = red[0] * (1.0f / (float)NB);
}

// ---------------------------------------------------------------------------
extern "C" void kernel_launch(void* const* d_in, const int* in_sizes, int n_in,
                              void* d_out, int out_size) {
    const float* x = (const float*)d_in[0];
    const float* y = (const float*)d_in[1];
    float* out = (float*)d_out;

    k_nxny<<<2048, 256>>>(x, y);
    k_init<<<32, 256>>>();
    dim3 gc(32, 32, 4);
    k_costd<<<gc, 256>>>(x, y);
    for (int it = 0; it < MAX_ITER; ++it) {
        k_prow<<<1024, 256>>>();
        k_qcol<<<128, 1024>>>();
        k_qfin<<<16, 512>>>();
    }
    k_final<<<1024, 256>>>();
    k_reduce<<<1, 256>>>(out);
}